// round 6
// baseline (speedup 1.0000x reference)
#include <cuda_runtime.h>
#include <cuda_bf16.h>
#include <cstdint>

#define NPOST 100000
#define NUSER 50000
#define NENT  20000
#define NEDGE_TOT 1550000
#define NSRC_TOT 400000     // sum of per-relation src node counts
#define NDST_TOT 420000     // sum of per-relation dst node counts
#define ACC_TOT  10880000   // (NPOST+NUSER+NENT)*64

typedef unsigned long long ull;

// ---------------- static device scratch ----------------
__device__ float g_h_post[NPOST * 64];
__device__ float g_h_user[NUSER * 64];
__device__ float g_h_ent [NENT  * 64];
__device__ float g_acc_post[NPOST * 64];
__device__ float g_acc_user[NUSER * 64];
__device__ float g_acc_ent [NENT  * 64];
__device__ float g_hs[51200000];        // concat per-relation hs [N_src][128]
__device__ float2 g_al_s[NSRC_TOT];
__device__ float2 g_al_d[NDST_TOT];
__device__ unsigned int g_m[NDST_TOT * 2];  // encoded float max per (dst,head)
__device__ float        g_ss[NDST_TOT * 2]; // softmax denom -> inverted in place
__device__ float2 g_p[NEDGE_TOT];           // unnormalized softmax numerators
__device__ float g_u[3072];             // folded attention vectors [l][r][side][h][64]

// ---------------- constant tables ----------------
__constant__ int c_EPFX[7]  = {0, 100000, 300000, 500000, 900000, 1300000, 1550000};
__constant__ int c_SOFF[6]  = {0, 50000, 100000, 200000, 250000, 300000};
__constant__ int c_DOFF[6]  = {0, 100000, 200000, 220000, 270000, 320000};
__constant__ int c_HSOFF[6] = {0, 6400000, 12800000, 25600000, 32000000, 38400000};
__constant__ int c_ALPFX[13] = {0, 50000, 100000, 200000, 250000, 300000, 400000,
                                500000, 600000, 620000, 670000, 720000, 820000};

struct EdgeParams { const int* src[6]; const int* dst[6]; };

// ---------------- helpers ----------------
__device__ __forceinline__ const float* src_x(int rel) {
    return (rel == 2 || rel == 5) ? g_h_post : g_h_user;
}
__device__ __forceinline__ const float* dst_x(int rel) {
    if (rel == 2) return g_h_ent;
    if (rel == 3 || rel == 4) return g_h_user;
    return g_h_post;
}
__device__ __forceinline__ float* out_acc(int rel) {
    if (rel == 2) return g_acc_ent;
    if (rel == 3 || rel == 4) return g_acc_user;
    return g_acc_post;
}
__device__ __forceinline__ float lrelu(float x) { return x > 0.0f ? x : 0.2f * x; }
__device__ __forceinline__ unsigned int encf(float f) {
    unsigned int u = __float_as_uint(f);
    return (u & 0x80000000u) ? ~u : (u | 0x80000000u);
}
__device__ __forceinline__ float decf(unsigned int u) {
    return (u & 0x80000000u) ? __uint_as_float(u & 0x7fffffffu) : __uint_as_float(~u);
}
__device__ __forceinline__ int edge_rel(int gid) {
    int rel = 0;
#pragma unroll
    for (int r = 1; r < 6; r++) if (gid >= c_EPFX[r]) rel = r;
    return rel;
}
__device__ __forceinline__ ull packf2(float lo, float hi) {
    ull r;
    asm("mov.b64 %0, {%1, %2};" : "=l"(r) : "f"(lo), "f"(hi));
    return r;
}
__device__ __forceinline__ ull fma2(ull a, ull b, ull c) {
    ull d;
    asm("fma.rn.f32x2 %0, %1, %2, %3;" : "=l"(d) : "l"(a), "l"(b), "l"(c));
    return d;
}

// ---------------- packed f32x2 tiled GEMM ----------------
// Y[n][m] = sum_k X[n][k] * W[m][k] (+ B[m]).  Block: 256 thr, 64 nodes x M cols.
// k-pair packing: both operands live pre-packed (k, k+1) in SMEM as u64, so the
// mainloop is pure FFMA2 + LDS.128 (no repack MOVs). K % 32 == 0.
template <int K, int M>
__device__ __forceinline__ void gemm_f32x2(const float* __restrict__ X,
                                           const float* __restrict__ W,
                                           const float* __restrict__ B,
                                           float* __restrict__ Y, int N)
{
    constexpr int KT = 32;
    constexpr int KP = KT / 2;          // 16 k-pairs per tile
    constexpr int TM = M / 16;          // cols per thread (4 or 8)
    constexpr int TPR = 256 / M;        // threads per W row (4 or 2)
    constexpr int LW  = KT / TPR;       // k's staged per thread (8 or 16)
    __shared__ ull Xs2[KP][64];
    __shared__ ull Ws2[KP][M + 2];

    const int t  = threadIdx.x;
    const int n0 = blockIdx.x * 64;
    const int tx = t & 15, ty = t >> 4;
    const int xn = t & 63, xk0 = (t >> 6) * 8;   // stages 8 k's = 4 pairs
    const int wm = t / TPR, wk0 = (t % TPR) * LW;

    ull acc[4][TM];
#pragma unroll
    for (int i = 0; i < 4; i++)
#pragma unroll
        for (int j = 0; j < TM; j++) acc[i][j] = 0ull;

    const bool xok = (n0 + xn) < N;

    for (int k0 = 0; k0 < K; k0 += KT) {
        // stage X: 2 float4 -> 4 packed k-pairs
        float4 a = make_float4(0.f, 0.f, 0.f, 0.f);
        float4 b = make_float4(0.f, 0.f, 0.f, 0.f);
        if (xok) {
            const float4* g = reinterpret_cast<const float4*>(
                X + (size_t)(n0 + xn) * K + k0 + xk0);
            a = g[0]; b = g[1];
        }
        {
            int r = xk0 >> 1;
            Xs2[r + 0][xn] = packf2(a.x, a.y);
            Xs2[r + 1][xn] = packf2(a.z, a.w);
            Xs2[r + 2][xn] = packf2(b.x, b.y);
            Xs2[r + 3][xn] = packf2(b.z, b.w);
        }
        // stage W
#pragma unroll
        for (int j = 0; j < LW; j += 4) {
            float4 w4 = *reinterpret_cast<const float4*>(
                W + (size_t)wm * K + k0 + wk0 + j);
            int r = (wk0 + j) >> 1;
            Ws2[r + 0][wm] = packf2(w4.x, w4.y);
            Ws2[r + 1][wm] = packf2(w4.z, w4.w);
        }
        __syncthreads();

#pragma unroll
        for (int kp = 0; kp < KP; kp++) {
            ull x2[4];
            {
                const ulonglong2* xp =
                    reinterpret_cast<const ulonglong2*>(&Xs2[kp][ty * 4]);
                ulonglong2 v0 = xp[0], v1 = xp[1];
                x2[0] = v0.x; x2[1] = v0.y; x2[2] = v1.x; x2[3] = v1.y;
            }
            ull w2[TM];
            {
                const ulonglong2* wp =
                    reinterpret_cast<const ulonglong2*>(&Ws2[kp][tx * TM]);
#pragma unroll
                for (int j = 0; j < TM / 2; j++) {
                    ulonglong2 v = wp[j];
                    w2[2 * j] = v.x; w2[2 * j + 1] = v.y;
                }
            }
#pragma unroll
            for (int i = 0; i < 4; i++)
#pragma unroll
                for (int j = 0; j < TM; j++)
                    acc[i][j] = fma2(x2[i], w2[j], acc[i][j]);
        }
        __syncthreads();
    }

    float bj[TM];
#pragma unroll
    for (int j = 0; j < TM; j++) bj[j] = B ? B[tx * TM + j] : 0.0f;
#pragma unroll
    for (int i = 0; i < 4; i++) {
        int n = n0 + ty * 4 + i;
        if (n < N) {
#pragma unroll
            for (int j = 0; j < TM; j += 4) {
                float4 v;
                float2 p0 = *reinterpret_cast<float2*>(&acc[i][j + 0]);
                float2 p1 = *reinterpret_cast<float2*>(&acc[i][j + 1]);
                float2 p2 = *reinterpret_cast<float2*>(&acc[i][j + 2]);
                float2 p3 = *reinterpret_cast<float2*>(&acc[i][j + 3]);
                v.x = p0.x + p0.y + bj[j + 0];
                v.y = p1.x + p1.y + bj[j + 1];
                v.z = p2.x + p2.y + bj[j + 2];
                v.w = p3.x + p3.y + bj[j + 3];
                *reinterpret_cast<float4*>(Y + (size_t)n * M + tx * TM + j) = v;
            }
        }
    }
}

// ---------------- kernels ----------------
__global__ void __launch_bounds__(256) proj_post_k(const float* X, const float* W, const float* B) {
    gemm_f32x2<768, 64>(X, W, B, g_h_post, NPOST);
}
__global__ void __launch_bounds__(256) proj_user_k(const float* X, const float* W, const float* B) {
    gemm_f32x2<32, 64>(X, W, B, g_h_user, NUSER);
}
__global__ void __launch_bounds__(256) proj_ent_k(const float* X, const float* W, const float* B) {
    gemm_f32x2<64, 64>(X, W, B, g_h_ent, NENT);
}
// hs = x_src @ W_src[l,rel].T : [N_src, 128]
__global__ void __launch_bounds__(256) hs_k(const float* __restrict__ Wsrc, int l, int rel, int N) {
    gemm_f32x2<64, 128>(src_x(rel), Wsrc + ((size_t)l * 6 + rel) * 8192, nullptr,
                        g_hs + c_HSOFF[rel], N);
}

// folded attention vectors: u[l][r][side][h][k] = sum_c a[l][r][h][c] * W[l][r][h*64+c][k]
__global__ void u_k(const float* __restrict__ Ws, const float* __restrict__ Wd,
                    const float* __restrict__ as_, const float* __restrict__ ad_) {
    int id = blockIdx.x * 256 + threadIdx.x;
    if (id >= 3072) return;
    int k = id & 63, h = (id >> 6) & 1, side = (id >> 7) & 1, rl = id >> 8;
    const float* a = (side ? ad_ : as_) + (size_t)rl * 128 + h * 64;
    const float* W = (side ? Wd : Ws) + (size_t)rl * 8192 + (size_t)h * 64 * 64;
    float u = 0.0f;
#pragma unroll 8
    for (int c = 0; c < 64; c++) u = fmaf(a[c], W[c * 64 + k], u);
    g_u[id] = u;
}

// attention scalars per node for all 12 (relation,side) tasks
__global__ void __launch_bounds__(256) al_k(int l) {
    int gid = blockIdx.x * 256 + threadIdx.x;
    if (gid >= 820000) return;
    int t = 0;
#pragma unroll
    for (int i = 1; i < 12; i++) if (gid >= c_ALPFX[i]) t = i;
    int n = gid - c_ALPFX[t];
    int side = (t >= 6) ? 1 : 0;
    int rel = side ? t - 6 : t;
    const float* xr = (side ? dst_x(rel) : src_x(rel)) + (size_t)n * 64;
    const float4* x4 = reinterpret_cast<const float4*>(xr);
    const float4* u4 = reinterpret_cast<const float4*>(
        g_u + ((size_t)(l * 6 + rel) * 2 + side) * 128);
    float a0 = 0.0f, a1 = 0.0f;
#pragma unroll
    for (int k = 0; k < 16; k++) {
        float4 xv = x4[k], u0 = u4[k], u1 = u4[16 + k];
        a0 = fmaf(xv.x, u0.x, fmaf(xv.y, u0.y, fmaf(xv.z, u0.z, fmaf(xv.w, u0.w, a0))));
        a1 = fmaf(xv.x, u1.x, fmaf(xv.y, u1.y, fmaf(xv.z, u1.z, fmaf(xv.w, u1.w, a1))));
    }
    float2 r; r.x = a0; r.y = a1;
    if (side) g_al_d[c_DOFF[rel] + n] = r;
    else      g_al_s[c_SOFF[rel] + n] = r;
}

// fused: zero softmax stats + init accumulators with summed gat biases
__global__ void reset_k(const float* __restrict__ gb, int l) {
    int gid = blockIdx.x * 256 + threadIdx.x;
    if (gid >= ACC_TOT) return;
    if (gid < NDST_TOT * 2) {
        g_m[gid] = 0u;      // encoded floor (< any finite float)
        g_ss[gid] = 0.0f;
    }
    int c = gid & 63;
    const float* b = gb + l * 384;  // [6][64]
    if (gid < NPOST * 64)
        g_acc_post[gid] = b[0 * 64 + c] + b[1 * 64 + c] + b[5 * 64 + c];
    else if (gid < (NPOST + NUSER) * 64)
        g_acc_user[gid - NPOST * 64] = b[3 * 64 + c] + b[4 * 64 + c];
    else
        g_acc_ent[gid - (NPOST + NUSER) * 64] = b[2 * 64 + c];
}

__global__ void __launch_bounds__(256) edge_max_k(EdgeParams p) {
    int gid = blockIdx.x * 256 + threadIdx.x;
    if (gid >= NEDGE_TOT) return;
    int rel = edge_rel(gid);
    int e = gid - c_EPFX[rel];
    int s = p.src[rel][e], d = p.dst[rel][e];
    float2 as = g_al_s[c_SOFF[rel] + s];
    float2 ad = g_al_d[c_DOFF[rel] + d];
    float e0 = lrelu(as.x + ad.x);
    float e1 = lrelu(as.y + ad.y);
    int di = (c_DOFF[rel] + d) * 2;
    atomicMax(&g_m[di + 0], encf(e0));
    atomicMax(&g_m[di + 1], encf(e1));
}

// exp(e - m), accumulate denominator, and stash numerator per edge
__global__ void __launch_bounds__(256) edge_sum_k(EdgeParams p) {
    int gid = blockIdx.x * 256 + threadIdx.x;
    if (gid >= NEDGE_TOT) return;
    int rel = edge_rel(gid);
    int e = gid - c_EPFX[rel];
    int s = p.src[rel][e], d = p.dst[rel][e];
    float2 as = g_al_s[c_SOFF[rel] + s];
    float2 ad = g_al_d[c_DOFF[rel] + d];
    float e0 = lrelu(as.x + ad.x);
    float e1 = lrelu(as.y + ad.y);
    int di = (c_DOFF[rel] + d) * 2;
    float p0 = __expf(e0 - decf(g_m[di + 0]));
    float p1 = __expf(e1 - decf(g_m[di + 1]));
    atomicAdd(&g_ss[di + 0], p0);
    atomicAdd(&g_ss[di + 1], p1);
    float2 pr; pr.x = p0; pr.y = p1;
    g_p[gid] = pr;
}

// invert denominators in place, folding in head-mean 0.5x
__global__ void inv_k() {
    int gid = blockIdx.x * 256 + threadIdx.x;
    if (gid >= NDST_TOT * 2) return;
    g_ss[gid] = 0.5f / (g_ss[gid] + 1e-16f);
}

// 16 threads per edge, 4 channels each; single float4 vector atomic per thread
__global__ void __launch_bounds__(256) edge_msg_k(EdgeParams p) {
    int gid = blockIdx.x * 256 + threadIdx.x;
    if (gid >= NEDGE_TOT * 16) return;
    int e = gid >> 4, c0 = (gid & 15) << 2;
    int rel = edge_rel(e);
    int eloc = e - c_EPFX[rel];
    int s = p.src[rel][eloc], d = p.dst[rel][eloc];
    float2 pr = g_p[e];
    int di = (c_DOFF[rel] + d) * 2;
    float a0 = pr.x * g_ss[di + 0];
    float a1 = pr.y * g_ss[di + 1];
    const float* hsrow = g_hs + c_HSOFF[rel] + (size_t)s * 128;
    float4 h0 = *reinterpret_cast<const float4*>(hsrow + c0);
    float4 h1 = *reinterpret_cast<const float4*>(hsrow + 64 + c0);
    float4 v;
    v.x = a0 * h0.x + a1 * h1.x;
    v.y = a0 * h0.y + a1 * h1.y;
    v.z = a0 * h0.z + a1 * h1.z;
    v.w = a0 * h0.w + a1 * h1.w;
    float4* acc = reinterpret_cast<float4*>(out_acc(rel) + (size_t)d * 64 + c0);
    atomicAdd(acc, v);
}

__global__ void relu_k() {
    int gid = blockIdx.x * 256 + threadIdx.x;
    if (gid >= ACC_TOT) return;
    if (gid < NPOST * 64)
        g_h_post[gid] = fmaxf(g_acc_post[gid], 0.0f);
    else if (gid < (NPOST + NUSER) * 64) {
        int i = gid - NPOST * 64;
        g_h_user[i] = fmaxf(g_acc_user[i], 0.0f);
    } else {
        int i = gid - (NPOST + NUSER) * 64;
        g_h_ent[i] = fmaxf(g_acc_ent[i], 0.0f);
    }
}

// classifier: one warp per post node
__global__ void __launch_bounds__(256) cls_k(const float* __restrict__ w1,
                                             const float* __restrict__ b1,
                                             const float* __restrict__ w2,
                                             const float* __restrict__ b2,
                                             float* __restrict__ out) {
    int gid = blockIdx.x * 256 + threadIdx.x;
    int n = gid >> 5, lane = gid & 31;
    if (n >= NPOST) return;
    const float4* x4 = reinterpret_cast<const float4*>(g_h_post + (size_t)n * 64);
    const float4* w4 = reinterpret_cast<const float4*>(w1 + (size_t)lane * 64);
    float a = 0.0f;
#pragma unroll
    for (int k = 0; k < 16; k++) {
        float4 xv = x4[k], wv = w4[k];
        a = fmaf(xv.x, wv.x, fmaf(xv.y, wv.y, fmaf(xv.z, wv.z, fmaf(xv.w, wv.w, a))));
    }
    float h = fmaxf(a + b1[lane], 0.0f) * w2[lane];
#pragma unroll
    for (int off = 16; off > 0; off >>= 1)
        h += __shfl_xor_sync(0xffffffffu, h, off);
    if (lane == 0) out[n] = h + b2[0];
}

// ---------------- launch ----------------
extern "C" void kernel_launch(void* const* d_in, const int* in_sizes, int n_in,
                              void* d_out, int out_size) {
    const float* x_post = (const float*)d_in[0];
    const float* x_user = (const float*)d_in[1];
    const float* x_ent  = (const float*)d_in[2];
    EdgeParams ep;
    for (int r = 0; r < 6; r++) {
        ep.src[r] = (const int*)d_in[3 + 2 * r];
        ep.dst[r] = (const int*)d_in[4 + 2 * r];
    }
    const float* post_w = (const float*)d_in[15];
    const float* post_b = (const float*)d_in[16];
    const float* user_w = (const float*)d_in[17];
    const float* user_b = (const float*)d_in[18];
    const float* ent_w  = (const float*)d_in[19];
    const float* ent_b  = (const float*)d_in[20];
    const float* W_src  = (const float*)d_in[21];
    const float* W_dst  = (const float*)d_in[22];
    const float* a_src  = (const float*)d_in[23];
    const float* a_dst  = (const float*)d_in[24];
    const float* gat_b  = (const float*)d_in[25];
    const float* cls_w1 = (const float*)d_in[26];
    const float* cls_b1 = (const float*)d_in[27];
    const float* cls_w2 = (const float*)d_in[28];
    const float* cls_b2 = (const float*)d_in[29];
    float* out = (float*)d_out;

    proj_post_k<<<1563, 256>>>(x_post, post_w, post_b);
    proj_user_k<<<782, 256>>>(x_user, user_w, user_b);
    proj_ent_k<<<313, 256>>>(x_ent, ent_w, ent_b);
    u_k<<<12, 256>>>(W_src, W_dst, a_src, a_dst);

    static const int hsN[6] = {50000, 50000, 100000, 50000, 50000, 100000};
    static const int hsG[6] = {782, 782, 1563, 782, 782, 1563};

    for (int l = 0; l < 2; l++) {
        for (int r = 0; r < 6; r++)
            hs_k<<<hsG[r], 256>>>(W_src, l, r, hsN[r]);
        al_k<<<3204, 256>>>(l);
        reset_k<<<42500, 256>>>(gat_b, l);
        edge_max_k<<<6055, 256>>>(ep);
        edge_sum_k<<<6055, 256>>>(ep);
        inv_k<<<3282, 256>>>();
        edge_msg_k<<<96875, 256>>>(ep);
        relu_k<<<42500, 256>>>();
    }
    cls_k<<<12500, 256>>>(cls_w1, cls_b1, cls_w2, cls_b2, out);
}

// round 7
// speedup vs baseline: 2.2426x; 2.2426x over previous
#include <cuda_runtime.h>
#include <cuda_bf16.h>
#include <cstdint>

#define NPOST 100000
#define NUSER 50000
#define NENT  20000
#define NEDGE_TOT 1550000
#define NSRC_TOT 400000     // sum of per-relation src node counts
#define NDST_TOT 420000     // sum of per-relation dst node counts
#define ACC_TOT  10880000   // (NPOST+NUSER+NENT)*64

// ---------------- static device scratch ----------------
__device__ float g_h_post[NPOST * 64];
__device__ float g_h_user[NUSER * 64];
__device__ float g_h_ent [NENT  * 64];
__device__ float g_acc_post[NPOST * 64];
__device__ float g_acc_user[NUSER * 64];
__device__ float g_acc_ent [NENT  * 64];
__device__ float g_hs[51200000];        // concat per-relation hs [N_src][128]
__device__ float2 g_al_s[NSRC_TOT];
__device__ float2 g_al_d[NDST_TOT];
__device__ unsigned int g_m[NDST_TOT * 2];  // encoded float max per (dst,head)
__device__ float        g_ss[NDST_TOT * 2]; // softmax denom -> inverted in place
__device__ float2 g_p[NEDGE_TOT];           // unnormalized softmax numerators
__device__ float g_u[3072];             // folded attention vectors [l][r][side][h][64]

// ---------------- constant tables ----------------
__constant__ int c_EPFX[7]  = {0, 100000, 300000, 500000, 900000, 1300000, 1550000};
__constant__ int c_SOFF[6]  = {0, 50000, 100000, 200000, 250000, 300000};
__constant__ int c_DOFF[6]  = {0, 100000, 200000, 220000, 270000, 320000};
__constant__ int c_HSOFF[6] = {0, 6400000, 12800000, 25600000, 32000000, 38400000};
__constant__ int c_ALPFX[13] = {0, 50000, 100000, 200000, 250000, 300000, 400000,
                                500000, 600000, 620000, 670000, 720000, 820000};

struct EdgeParams { const int* src[6]; const int* dst[6]; };

// ---------------- helpers ----------------
__device__ __forceinline__ const float* src_x(int rel) {
    return (rel == 2 || rel == 5) ? g_h_post : g_h_user;
}
__device__ __forceinline__ const float* dst_x(int rel) {
    if (rel == 2) return g_h_ent;
    if (rel == 3 || rel == 4) return g_h_user;
    return g_h_post;
}
__device__ __forceinline__ float* out_acc(int rel) {
    if (rel == 2) return g_acc_ent;
    if (rel == 3 || rel == 4) return g_acc_user;
    return g_acc_post;
}
__device__ __forceinline__ float lrelu(float x) { return x > 0.0f ? x : 0.2f * x; }
__device__ __forceinline__ unsigned int encf(float f) {
    unsigned int u = __float_as_uint(f);
    return (u & 0x80000000u) ? ~u : (u | 0x80000000u);
}
__device__ __forceinline__ float decf(unsigned int u) {
    return (u & 0x80000000u) ? __uint_as_float(u & 0x7fffffffu) : __uint_as_float(~u);
}
__device__ __forceinline__ int edge_rel(int gid) {
    int rel = 0;
#pragma unroll
    for (int r = 1; r < 6; r++) if (gid >= c_EPFX[r]) rel = r;
    return rel;
}

// ---------------- tiled GEMM: Y[n][m] = sum_k X[n][k]*W[m][k] (+ B[m]) ----------------
// Block = 256 threads handles 64 nodes x M cols. K, M compile-time. K % 32 == 0.
// (round-5 scalar-FFMA version — the f32x2 rewrite regressed 2x due to
//  forced register-pair allocation; reverted.)
template <int K, int M>
__device__ __forceinline__ void gemm_device(const float* __restrict__ X,
                                            const float* __restrict__ W,
                                            const float* __restrict__ B,
                                            float* __restrict__ Y, int N)
{
    constexpr int KT  = 32;
    constexpr int TM  = M / 16;        // cols per thread (4 or 8)
    constexpr int TPR = 256 / M;       // threads per W row
    constexpr int LW  = 32 / TPR;      // k's per thread for W staging
    __shared__ float Xs[KT * 64];
    __shared__ float Ws[KT * (M + 4)];

    const int t  = threadIdx.x;
    const int n0 = blockIdx.x * 64;
    const int tx = t & 15, ty = t >> 4;
    const int xn = t & 63, xk0 = (t >> 6) * 8;
    const int wm = t / TPR, wk0 = (t % TPR) * LW;

    float acc[4][TM];
#pragma unroll
    for (int i = 0; i < 4; i++)
#pragma unroll
        for (int j = 0; j < TM; j++) acc[i][j] = 0.0f;

    const bool xok = (n0 + xn) < N;

    for (int k0 = 0; k0 < K; k0 += KT) {
        float4 a = make_float4(0.f, 0.f, 0.f, 0.f);
        float4 b = make_float4(0.f, 0.f, 0.f, 0.f);
        if (xok) {
            const float4* g = reinterpret_cast<const float4*>(
                X + (size_t)(n0 + xn) * K + k0 + xk0);
            a = g[0]; b = g[1];
        }
        Xs[(xk0 + 0) * 64 + xn] = a.x; Xs[(xk0 + 1) * 64 + xn] = a.y;
        Xs[(xk0 + 2) * 64 + xn] = a.z; Xs[(xk0 + 3) * 64 + xn] = a.w;
        Xs[(xk0 + 4) * 64 + xn] = b.x; Xs[(xk0 + 5) * 64 + xn] = b.y;
        Xs[(xk0 + 6) * 64 + xn] = b.z; Xs[(xk0 + 7) * 64 + xn] = b.w;

#pragma unroll
        for (int j = 0; j < LW; j += 4) {
            float4 w4 = *reinterpret_cast<const float4*>(
                W + (size_t)wm * K + k0 + wk0 + j);
            Ws[(wk0 + j + 0) * (M + 4) + wm] = w4.x;
            Ws[(wk0 + j + 1) * (M + 4) + wm] = w4.y;
            Ws[(wk0 + j + 2) * (M + 4) + wm] = w4.z;
            Ws[(wk0 + j + 3) * (M + 4) + wm] = w4.w;
        }
        __syncthreads();

#pragma unroll
        for (int kk = 0; kk < KT; kk++) {
            float4 xv4 = *reinterpret_cast<const float4*>(&Xs[kk * 64 + ty * 4]);
            float xv[4] = {xv4.x, xv4.y, xv4.z, xv4.w};
            float wv[TM];
#pragma unroll
            for (int j = 0; j < TM; j += 4) {
                float4 w4 = *reinterpret_cast<const float4*>(
                    &Ws[kk * (M + 4) + tx * TM + j]);
                wv[j] = w4.x; wv[j + 1] = w4.y; wv[j + 2] = w4.z; wv[j + 3] = w4.w;
            }
#pragma unroll
            for (int i = 0; i < 4; i++)
#pragma unroll
                for (int j = 0; j < TM; j++)
                    acc[i][j] = fmaf(xv[i], wv[j], acc[i][j]);
        }
        __syncthreads();
    }

    float bj[TM];
#pragma unroll
    for (int j = 0; j < TM; j++) bj[j] = B ? B[tx * TM + j] : 0.0f;
#pragma unroll
    for (int i = 0; i < 4; i++) {
        int n = n0 + ty * 4 + i;
        if (n < N) {
#pragma unroll
            for (int j = 0; j < TM; j += 4) {
                float4 v;
                v.x = acc[i][j + 0] + bj[j + 0];
                v.y = acc[i][j + 1] + bj[j + 1];
                v.z = acc[i][j + 2] + bj[j + 2];
                v.w = acc[i][j + 3] + bj[j + 3];
                *reinterpret_cast<float4*>(Y + (size_t)n * M + tx * TM + j) = v;
            }
        }
    }
}

// ---------------- kernels ----------------
__global__ void __launch_bounds__(256) proj_post_k(const float* X, const float* W, const float* B) {
    gemm_device<768, 64>(X, W, B, g_h_post, NPOST);
}
__global__ void __launch_bounds__(256) proj_user_k(const float* X, const float* W, const float* B) {
    gemm_device<32, 64>(X, W, B, g_h_user, NUSER);
}
__global__ void __launch_bounds__(256) proj_ent_k(const float* X, const float* W, const float* B) {
    gemm_device<64, 64>(X, W, B, g_h_ent, NENT);
}
// hs = x_src @ W_src[l,rel].T : [N_src, 128]
__global__ void __launch_bounds__(256) hs_k(const float* __restrict__ Wsrc, int l, int rel, int N) {
    gemm_device<64, 128>(src_x(rel), Wsrc + ((size_t)l * 6 + rel) * 8192, nullptr,
                         g_hs + c_HSOFF[rel], N);
}

// folded attention vectors: u[l][r][side][h][k] = sum_c a[l][r][h][c] * W[l][r][h*64+c][k]
__global__ void u_k(const float* __restrict__ Ws, const float* __restrict__ Wd,
                    const float* __restrict__ as_, const float* __restrict__ ad_) {
    int id = blockIdx.x * 256 + threadIdx.x;
    if (id >= 3072) return;
    int k = id & 63, h = (id >> 6) & 1, side = (id >> 7) & 1, rl = id >> 8;
    const float* a = (side ? ad_ : as_) + (size_t)rl * 128 + h * 64;
    const float* W = (side ? Wd : Ws) + (size_t)rl * 8192 + (size_t)h * 64 * 64;
    float u = 0.0f;
#pragma unroll 8
    for (int c = 0; c < 64; c++) u = fmaf(a[c], W[c * 64 + k], u);
    g_u[id] = u;
}

// attention scalars per node for all 12 (relation,side) tasks
__global__ void __launch_bounds__(256) al_k(int l) {
    int gid = blockIdx.x * 256 + threadIdx.x;
    if (gid >= 820000) return;
    int t = 0;
#pragma unroll
    for (int i = 1; i < 12; i++) if (gid >= c_ALPFX[i]) t = i;
    int n = gid - c_ALPFX[t];
    int side = (t >= 6) ? 1 : 0;
    int rel = side ? t - 6 : t;
    const float* xr = (side ? dst_x(rel) : src_x(rel)) + (size_t)n * 64;
    const float4* x4 = reinterpret_cast<const float4*>(xr);
    const float4* u4 = reinterpret_cast<const float4*>(
        g_u + ((size_t)(l * 6 + rel) * 2 + side) * 128);
    float a0 = 0.0f, a1 = 0.0f;
#pragma unroll
    for (int k = 0; k < 16; k++) {
        float4 xv = x4[k], u0 = u4[k], u1 = u4[16 + k];
        a0 = fmaf(xv.x, u0.x, fmaf(xv.y, u0.y, fmaf(xv.z, u0.z, fmaf(xv.w, u0.w, a0))));
        a1 = fmaf(xv.x, u1.x, fmaf(xv.y, u1.y, fmaf(xv.z, u1.z, fmaf(xv.w, u1.w, a1))));
    }
    float2 r; r.x = a0; r.y = a1;
    if (side) g_al_d[c_DOFF[rel] + n] = r;
    else      g_al_s[c_SOFF[rel] + n] = r;
}

// fused: zero softmax stats + init accumulators with summed gat biases
__global__ void reset_k(const float* __restrict__ gb, int l) {
    int gid = blockIdx.x * 256 + threadIdx.x;
    if (gid >= ACC_TOT) return;
    if (gid < NDST_TOT * 2) {
        g_m[gid] = 0u;      // encoded floor (< any finite float)
        g_ss[gid] = 0.0f;
    }
    int c = gid & 63;
    const float* b = gb + l * 384;  // [6][64]
    if (gid < NPOST * 64)
        g_acc_post[gid] = b[0 * 64 + c] + b[1 * 64 + c] + b[5 * 64 + c];
    else if (gid < (NPOST + NUSER) * 64)
        g_acc_user[gid - NPOST * 64] = b[3 * 64 + c] + b[4 * 64 + c];
    else
        g_acc_ent[gid - (NPOST + NUSER) * 64] = b[2 * 64 + c];
}

__global__ void __launch_bounds__(256) edge_max_k(EdgeParams p) {
    int gid = blockIdx.x * 256 + threadIdx.x;
    if (gid >= NEDGE_TOT) return;
    int rel = edge_rel(gid);
    int e = gid - c_EPFX[rel];
    int s = p.src[rel][e], d = p.dst[rel][e];
    float2 as = g_al_s[c_SOFF[rel] + s];
    float2 ad = g_al_d[c_DOFF[rel] + d];
    float e0 = lrelu(as.x + ad.x);
    float e1 = lrelu(as.y + ad.y);
    int di = (c_DOFF[rel] + d) * 2;
    atomicMax(&g_m[di + 0], encf(e0));
    atomicMax(&g_m[di + 1], encf(e1));
}

// exp(e - m), accumulate denominator, and stash numerator per edge
__global__ void __launch_bounds__(256) edge_sum_k(EdgeParams p) {
    int gid = blockIdx.x * 256 + threadIdx.x;
    if (gid >= NEDGE_TOT) return;
    int rel = edge_rel(gid);
    int e = gid - c_EPFX[rel];
    int s = p.src[rel][e], d = p.dst[rel][e];
    float2 as = g_al_s[c_SOFF[rel] + s];
    float2 ad = g_al_d[c_DOFF[rel] + d];
    float e0 = lrelu(as.x + ad.x);
    float e1 = lrelu(as.y + ad.y);
    int di = (c_DOFF[rel] + d) * 2;
    float p0 = __expf(e0 - decf(g_m[di + 0]));
    float p1 = __expf(e1 - decf(g_m[di + 1]));
    atomicAdd(&g_ss[di + 0], p0);
    atomicAdd(&g_ss[di + 1], p1);
    float2 pr; pr.x = p0; pr.y = p1;
    g_p[gid] = pr;
}

// invert denominators in place, folding in head-mean 0.5x
__global__ void inv_k() {
    int gid = blockIdx.x * 256 + threadIdx.x;
    if (gid >= NDST_TOT * 2) return;
    g_ss[gid] = 0.5f / (g_ss[gid] + 1e-16f);
}

// 16 threads per edge, 4 channels each; single float4 vector atomic per thread
__global__ void __launch_bounds__(256) edge_msg_k(EdgeParams p) {
    int gid = blockIdx.x * 256 + threadIdx.x;
    if (gid >= NEDGE_TOT * 16) return;
    int e = gid >> 4, c0 = (gid & 15) << 2;
    int rel = edge_rel(e);
    int eloc = e - c_EPFX[rel];
    int s = p.src[rel][eloc], d = p.dst[rel][eloc];
    float2 pr = g_p[e];
    int di = (c_DOFF[rel] + d) * 2;
    float a0 = pr.x * g_ss[di + 0];
    float a1 = pr.y * g_ss[di + 1];
    const float* hsrow = g_hs + c_HSOFF[rel] + (size_t)s * 128;
    float4 h0 = *reinterpret_cast<const float4*>(hsrow + c0);
    float4 h1 = *reinterpret_cast<const float4*>(hsrow + 64 + c0);
    float4 v;
    v.x = a0 * h0.x + a1 * h1.x;
    v.y = a0 * h0.y + a1 * h1.y;
    v.z = a0 * h0.z + a1 * h1.z;
    v.w = a0 * h0.w + a1 * h1.w;
    float4* acc = reinterpret_cast<float4*>(out_acc(rel) + (size_t)d * 64 + c0);
    atomicAdd(acc, v);
}

__global__ void relu_k() {
    int gid = blockIdx.x * 256 + threadIdx.x;
    if (gid >= ACC_TOT) return;
    if (gid < NPOST * 64)
        g_h_post[gid] = fmaxf(g_acc_post[gid], 0.0f);
    else if (gid < (NPOST + NUSER) * 64) {
        int i = gid - NPOST * 64;
        g_h_user[i] = fmaxf(g_acc_user[i], 0.0f);
    } else {
        int i = gid - (NPOST + NUSER) * 64;
        g_h_ent[i] = fmaxf(g_acc_ent[i], 0.0f);
    }
}

// classifier: one warp per post node
__global__ void __launch_bounds__(256) cls_k(const float* __restrict__ w1,
                                             const float* __restrict__ b1,
                                             const float* __restrict__ w2,
                                             const float* __restrict__ b2,
                                             float* __restrict__ out) {
    int gid = blockIdx.x * 256 + threadIdx.x;
    int n = gid >> 5, lane = gid & 31;
    if (n >= NPOST) return;
    const float4* x4 = reinterpret_cast<const float4*>(g_h_post + (size_t)n * 64);
    const float4* w4 = reinterpret_cast<const float4*>(w1 + (size_t)lane * 64);
    float a = 0.0f;
#pragma unroll
    for (int k = 0; k < 16; k++) {
        float4 xv = x4[k], wv = w4[k];
        a = fmaf(xv.x, wv.x, fmaf(xv.y, wv.y, fmaf(xv.z, wv.z, fmaf(xv.w, wv.w, a))));
    }
    float h = fmaxf(a + b1[lane], 0.0f) * w2[lane];
#pragma unroll
    for (int off = 16; off > 0; off >>= 1)
        h += __shfl_xor_sync(0xffffffffu, h, off);
    if (lane == 0) out[n] = h + b2[0];
}

// ---------------- launch ----------------
extern "C" void kernel_launch(void* const* d_in, const int* in_sizes, int n_in,
                              void* d_out, int out_size) {
    const float* x_post = (const float*)d_in[0];
    const float* x_user = (const float*)d_in[1];
    const float* x_ent  = (const float*)d_in[2];
    EdgeParams ep;
    for (int r = 0; r < 6; r++) {
        ep.src[r] = (const int*)d_in[3 + 2 * r];
        ep.dst[r] = (const int*)d_in[4 + 2 * r];
    }
    const float* post_w = (const float*)d_in[15];
    const float* post_b = (const float*)d_in[16];
    const float* user_w = (const float*)d_in[17];
    const float* user_b = (const float*)d_in[18];
    const float* ent_w  = (const float*)d_in[19];
    const float* ent_b  = (const float*)d_in[20];
    const float* W_src  = (const float*)d_in[21];
    const float* W_dst  = (const float*)d_in[22];
    const float* a_src  = (const float*)d_in[23];
    const float* a_dst  = (const float*)d_in[24];
    const float* gat_b  = (const float*)d_in[25];
    const float* cls_w1 = (const float*)d_in[26];
    const float* cls_b1 = (const float*)d_in[27];
    const float* cls_w2 = (const float*)d_in[28];
    const float* cls_b2 = (const float*)d_in[29];
    float* out = (float*)d_out;

    proj_post_k<<<1563, 256>>>(x_post, post_w, post_b);
    proj_user_k<<<782, 256>>>(x_user, user_w, user_b);
    proj_ent_k<<<313, 256>>>(x_ent, ent_w, ent_b);
    u_k<<<12, 256>>>(W_src, W_dst, a_src, a_dst);

    static const int hsN[6] = {50000, 50000, 100000, 50000, 50000, 100000};
    static const int hsG[6] = {782, 782, 1563, 782, 782, 1563};

    for (int l = 0; l < 2; l++) {
        for (int r = 0; r < 6; r++)
            hs_k<<<hsG[r], 256>>>(W_src, l, r, hsN[r]);
        al_k<<<3204, 256>>>(l);
        reset_k<<<42500, 256>>>(gat_b, l);
        edge_max_k<<<6055, 256>>>(ep);
        edge_sum_k<<<6055, 256>>>(ep);
        inv_k<<<3282, 256>>>();
        edge_msg_k<<<96875, 256>>>(ep);
        relu_k<<<42500, 256>>>();
    }
    cls_k<<<12500, 256>>>(cls_w1, cls_b1, cls_w2, cls_b2, out);
}